// round 9
// baseline (speedup 1.0000x reference)
#include <cuda_runtime.h>
#include <cstdint>

// ---------------- problem constants ----------------
#define BATCH 4
#define SEQ 2048
#define EMB 2048
#define NH 16
#define DH 128
#define BH (BATCH * NH)          // 64
#define SD (SEQ * DH)            // 262144
#define SS ((size_t)SEQ * SEQ)
#define INVSQ 0.08838834764831845f   // 1/sqrt(128)

// scratch (allocation-free rule)
__device__ float g_q[(size_t)BH * SD];
__device__ float g_k[(size_t)BH * SD];
__device__ float g_v[(size_t)BH * SD];
__device__ float g_scores[(size_t)BH * SS];
__device__ float g_ctx[(size_t)BATCH * SEQ * EMB];
__device__ float g_m[(size_t)BH * SEQ];             // per-row max
__device__ float g_l[(size_t)BH * SEQ];             // per-row exp-sum

__device__ __forceinline__ float rtf32(float x) {
    float y;
    asm("cvt.rna.tf32.f32 %0, %1;" : "=f"(y) : "f"(x));
    return y;
}
__device__ __forceinline__ uint32_t rtf32u(uint32_t x) {
    return __float_as_uint(rtf32(__uint_as_float(x)));
}
__device__ __forceinline__ uint32_t smem_u32(const void* p) {
    return (uint32_t)__cvta_generic_to_shared(p);
}
__device__ __forceinline__ void cp16(uint32_t s, const void* g) {
    asm volatile("cp.async.cg.shared.global [%0], [%1], 16;\n" :: "r"(s), "l"(g));
}
__device__ __forceinline__ void ldsm4(uint32_t* r, uint32_t addr) {
    asm volatile("ldmatrix.sync.aligned.m8n8.x4.shared.b16 {%0,%1,%2,%3}, [%4];"
                 : "=r"(r[0]), "=r"(r[1]), "=r"(r[2]), "=r"(r[3]) : "r"(addr));
}
__device__ __forceinline__ void mma_tf32(float* c, const uint32_t* a, const uint32_t* b) {
    asm volatile(
        "mma.sync.aligned.m16n8k8.row.col.f32.tf32.tf32.f32 "
        "{%0,%1,%2,%3},{%4,%5,%6,%7},{%8,%9},{%0,%1,%2,%3};"
        : "+f"(c[0]), "+f"(c[1]), "+f"(c[2]), "+f"(c[3])
        : "r"(a[0]), "r"(a[1]), "r"(a[2]), "r"(a[3]), "r"(b[0]), "r"(b[1]));
}

// ---------------------------------------------------------------------------
// Generic TF32 mma.sync GEMM, CTA 128x128, 256 threads = 8 warps (4m x 2n),
// warp tile 32x64, BK=32, 3-stage cp.async pipeline, ldmatrix operand loads.
// MODE 0: fused QKV proj; grid.x=48: sel=bx>>4 picks Wq/Wk/Wv, head=bx&15.
//         A=x (raw fp32, cvt-in-loop), B=W (raw, cvt-in-loop). Rounded scatter out.
// MODE 2: ctx = softmax(S) V per (b,h); exp applied in-smem (stats g_m/g_l),
//         K truncated causally. Rounded store.
// MODE 3: out proj C = ctx * Wo^T + bias (B raw, cvt-in-loop).
// ---------------------------------------------------------------------------
#define BK 32
#define SA 36                                  // tile row stride in floats
#define B_OFF (128 * SA)                       // words
#define STAGE_WORDS (2 * 128 * SA)             // 9216 words
#define NSTAGE 3
#define STAT_OFF (NSTAGE * STAGE_WORDS)        // words: [m:128][rl:128]
#define SMEM_BYTES ((STAT_OFF + 256) * 4)      // 111616

template<int MODE>
__global__ __launch_bounds__(256)
void gemm_tc(const float* __restrict__ Aext, const float* __restrict__ Bq,
             const float* __restrict__ Bk, const float* __restrict__ Bv,
             float* __restrict__ Oext, const float* __restrict__ bias)
{
    extern __shared__ float dyn[];

    const int tid  = threadIdx.x;
    const int wid  = tid >> 5;
    const int lane = tid & 31;
    const int wr   = wid >> 1;     // 4 m-groups of 32
    const int wc   = wid & 1;      // 2 n-groups of 64
    const int lq   = lane >> 3;
    const int lr   = lane & 7;
    const int m0   = blockIdx.y * 128;
    const int z    = blockIdx.z;
    const int sel  = (MODE == 0) ? (blockIdx.x >> 4) : 0;
    const int n0   = (MODE == 0) ? (blockIdx.x & 15) * 128 : blockIdx.x * 128;

    const float* A;  int lda;
    const float* Bm; int ldb;
    int Ktot;
    if (MODE == 0)      { A = Aext;                      lda = EMB;
                          Bm = (sel == 0 ? Bq : sel == 1 ? Bk : Bv); ldb = EMB; Ktot = EMB; }
    else if (MODE == 2) { A = g_scores + (size_t)z * SS; lda = SEQ; Bm = g_v + (size_t)z * SD; ldb = DH;  Ktot = m0 + 128; }
    else                { A = g_ctx;                     lda = EMB; Bm = Bq;                   ldb = EMB; Ktot = EMB; }
    const int T = Ktot / BK;

    const uint32_t sbase = smem_u32(dyn);

    if (MODE == 2 && tid < 128) {
        float mv = g_m[(size_t)z * SEQ + m0 + tid];
        float lv = g_l[(size_t)z * SEQ + m0 + tid];
        dyn[STAT_OFF + tid] = mv;
        dyn[STAT_OFF + 128 + tid] = 1.0f / lv;
    }

    auto load_stage = [&](int buf, int t) {
        const int k0 = t * BK;
        const uint32_t sa = sbase + (uint32_t)(buf * STAGE_WORDS) * 4u;
        #pragma unroll
        for (int i = 0; i < 4; i++) {
            int id = tid + i * 256;
            int r = id >> 3, c4 = id & 7;
            cp16(sa + (uint32_t)(r * SA + c4 * 4) * 4u,
                 A + (size_t)(m0 + r) * lda + k0 + c4 * 4);
        }
        if (MODE != 2) {
            #pragma unroll
            for (int i = 0; i < 4; i++) {
                int id = tid + i * 256;
                int r = id >> 3, c4 = id & 7;
                cp16(sa + (uint32_t)(B_OFF + r * SA + c4 * 4) * 4u,
                     Bm + (size_t)(n0 + r) * ldb + k0 + c4 * 4);
            }
        } else {
            float* bp = dyn + buf * STAGE_WORDS + B_OFF;
            #pragma unroll
            for (int i = 0; i < 4; i++) {
                int id = tid + i * 256;
                int n4 = id & 31, k = id >> 5;
                float4 v = *(const float4*)(Bm + (size_t)(k0 + k) * DH + n4 * 4);
                bp[(n4 * 4 + 0) * SA + k] = v.x;
                bp[(n4 * 4 + 1) * SA + k] = v.y;
                bp[(n4 * 4 + 2) * SA + k] = v.z;
                bp[(n4 * 4 + 3) * SA + k] = v.w;
            }
        }
        asm volatile("cp.async.commit_group;\n");
    };

    float acc[2][8][4];
    #pragma unroll
    for (int i = 0; i < 2; i++)
        #pragma unroll
        for (int j = 0; j < 8; j++)
            #pragma unroll
            for (int e = 0; e < 4; e++) acc[i][j][e] = 0.0f;

    load_stage(0, 0);
    load_stage(1, 1);

    const int a_row = wr * 32 + (lq & 1) * 8 + lr;
    const int a_kq  = (lq >> 1) * 4;
    const int b_row = wc * 64 + (lq >> 1) * 8 + lr;
    const int b_kq  = (lq & 1) * 4;

    for (int t = 0; t < T; t++) {
        asm volatile("cp.async.wait_group 1;\n" ::: "memory");
        __syncthreads();

        if (t + 2 < T) load_stage((t + 2) % NSTAGE, t + 2);
        else asm volatile("cp.async.commit_group;\n");

        if (MODE == 2) {
            float* ap = dyn + (t % NSTAGE) * STAGE_WORDS;
            const int k0t = t * BK;
            #pragma unroll
            for (int i = 0; i < 4; i++) {
                int id = tid + i * 256;
                int r = id >> 3, c = (id & 7) * 4;
                int grow = m0 + r;
                float mv = dyn[STAT_OFF + r];
                float rl = dyn[STAT_OFF + 128 + r];
                float4 v = *(float4*)(ap + r * SA + c);
                int gc = k0t + c;
                v.x = (gc + 0 <= grow) ? rtf32(__expf((v.x - mv) * INVSQ) * rl) : 0.0f;
                v.y = (gc + 1 <= grow) ? rtf32(__expf((v.y - mv) * INVSQ) * rl) : 0.0f;
                v.z = (gc + 2 <= grow) ? rtf32(__expf((v.z - mv) * INVSQ) * rl) : 0.0f;
                v.w = (gc + 3 <= grow) ? rtf32(__expf((v.w - mv) * INVSQ) * rl) : 0.0f;
                *(float4*)(ap + r * SA + c) = v;
            }
            __syncthreads();
        }

        const uint32_t st = sbase + (uint32_t)((t % NSTAGE) * STAGE_WORDS) * 4u;

        #pragma unroll
        for (int ks = 0; ks < 4; ks++) {
            uint32_t a[2][4], b[8][2];
            #pragma unroll
            for (int i = 0; i < 2; i++)
                ldsm4(a[i], st + (uint32_t)((a_row + i * 16) * SA + ks * 8 + a_kq) * 4u);
            #pragma unroll
            for (int u = 0; u < 4; u++) {
                uint32_t r[4];
                ldsm4(r, st + (uint32_t)(B_OFF + (b_row + u * 16) * SA + ks * 8 + b_kq) * 4u);
                b[2 * u][0] = r[0]; b[2 * u][1] = r[1];
                b[2 * u + 1][0] = r[2]; b[2 * u + 1][1] = r[3];
            }
            if (MODE == 0) {   // raw x, raw W -> round to tf32 in-register
                #pragma unroll
                for (int i = 0; i < 2; i++)
                    #pragma unroll
                    for (int e = 0; e < 4; e++) a[i][e] = rtf32u(a[i][e]);
            }
            if (MODE == 0 || MODE == 3) {   // raw W -> round
                #pragma unroll
                for (int j = 0; j < 8; j++) {
                    b[j][0] = rtf32u(b[j][0]); b[j][1] = rtf32u(b[j][1]);
                }
            }
            #pragma unroll
            for (int i = 0; i < 2; i++)
                #pragma unroll
                for (int j = 0; j < 8; j++)
                    mma_tf32(acc[i][j], a[i], b[j]);
        }
    }

    // ---- epilogue ----
    float* base; size_t ldo;
    bool do_round;
    if (MODE == 0) {
        int b = m0 >> 11;
        float* qkv = (sel == 0 ? g_q : sel == 1 ? g_k : g_v);
        base = qkv + ((size_t)(b * NH + (blockIdx.x & 15))) * SD + (size_t)(m0 & (SEQ - 1)) * DH;
        ldo = DH;  do_round = true;
    } else if (MODE == 2) {
        int b = z >> 4, h = z & 15;
        base = g_ctx + (size_t)b * SEQ * EMB + (size_t)m0 * EMB + h * DH;
        ldo = EMB; do_round = true;
    } else {
        base = Oext + (size_t)m0 * EMB + n0;
        ldo = EMB; do_round = false;
    }

    const int er = lane >> 2;
    const int ec = (lane & 3) * 2;
    #pragma unroll
    for (int i = 0; i < 2; i++)
        #pragma unroll
        for (int j = 0; j < 8; j++) {
            int lrow = wr * 32 + i * 16 + er;
            int lcol = wc * 64 + j * 8 + ec;
            float2 v0, v1;
            if (do_round) {
                v0 = make_float2(rtf32(acc[i][j][0]), rtf32(acc[i][j][1]));
                v1 = make_float2(rtf32(acc[i][j][2]), rtf32(acc[i][j][3]));
            } else {
                v0 = make_float2(acc[i][j][0], acc[i][j][1]);
                v1 = make_float2(acc[i][j][2], acc[i][j][3]);
            }
            if (MODE == 3) {
                float b0 = bias[n0 + lcol], b1 = bias[n0 + lcol + 1];
                v0.x += b0; v0.y += b1; v1.x += b0; v1.y += b1;
            }
            *(float2*)(base + (size_t)lrow * ldo + lcol) = v0;
            *(float2*)(base + (size_t)(lrow + 8) * ldo + lcol) = v1;
        }
}

// ---------------------------------------------------------------------------
// scores = Q K^T, row-panel CTA: one CTA per (q-panel, bh). Q panel (128x128)
// loaded to smem once; K chunks streamed in a 3-slot ring across an internal
// n-tile loop (bx = 0..by). Continuous pipeline across n-tiles.
// ---------------------------------------------------------------------------
#define RP_ACHUNK (128 * SA)                    // words per 32-k A chunk
#define RP_AWORDS (4 * RP_ACHUNK)               // full 128x128 panel
#define RP_BSLOT  (128 * SA)                    // words per B stage
#define RP_SMEM ((RP_AWORDS + 3 * RP_BSLOT) * 4)   // 129024 B

__global__ __launch_bounds__(256)
void scores_rowpanel()
{
    extern __shared__ float dyn[];
    const int tid  = threadIdx.x;
    const int wid  = tid >> 5;
    const int lane = tid & 31;
    const int wr   = wid >> 1;
    const int wc   = wid & 1;
    const int lq   = lane >> 3;
    const int lr   = lane & 7;
    const int by   = blockIdx.x;
    const int z    = blockIdx.y;
    const int m0   = by * 128;

    const float* A = g_q + (size_t)z * SD;
    const float* B = g_k + (size_t)z * SD;
    const uint32_t sbase = smem_u32(dyn);

    // A panel: 4 chunks of [128 rows][32 k], 16 cp16/thread
    #pragma unroll
    for (int i = 0; i < 16; i++) {
        int id = tid + i * 256;
        int r = id >> 5, kc = (id >> 3) & 3, c4 = id & 7;
        cp16(sbase + (uint32_t)(kc * RP_ACHUNK + r * SA + c4 * 4) * 4u,
             A + (size_t)(m0 + r) * DH + kc * 32 + c4 * 4);
    }
    asm volatile("cp.async.commit_group;\n");

    const int S = 4 * (by + 1);   // total (bx, kc) steps

    auto load_b = [&](int s) {
        int bx = s >> 2, kc = s & 3;
        uint32_t sb = sbase + (uint32_t)(RP_AWORDS + (s % 3) * RP_BSLOT) * 4u;
        #pragma unroll
        for (int i = 0; i < 4; i++) {
            int id = tid + i * 256;
            int r = id >> 3, c4 = id & 7;
            cp16(sb + (uint32_t)(r * SA + c4 * 4) * 4u,
                 B + (size_t)(bx * 128 + r) * DH + kc * 32 + c4 * 4);
        }
        asm volatile("cp.async.commit_group;\n");
    };

    load_b(0);
    load_b(1);

    float acc[2][8][4];
    #pragma unroll
    for (int i = 0; i < 2; i++)
        #pragma unroll
        for (int j = 0; j < 8; j++)
            #pragma unroll
            for (int e = 0; e < 4; e++) acc[i][j][e] = 0.0f;

    const int a_row = wr * 32 + (lq & 1) * 8 + lr;
    const int a_kq  = (lq >> 1) * 4;
    const int b_row = wc * 64 + (lq >> 1) * 8 + lr;
    const int b_kq  = (lq & 1) * 4;
    const int er = lane >> 2;
    const int ec = (lane & 3) * 2;

    for (int s = 0; s < S; s++) {
        asm volatile("cp.async.wait_group 1;\n" ::: "memory");
        __syncthreads();

        if (s + 2 < S) load_b(s + 2);
        else asm volatile("cp.async.commit_group;\n");

        const uint32_t sa = sbase + (uint32_t)((s & 3) * RP_ACHUNK) * 4u;
        const uint32_t sb = sbase + (uint32_t)(RP_AWORDS + (s % 3) * RP_BSLOT) * 4u;

        #pragma unroll
        for (int ks = 0; ks < 4; ks++) {
            uint32_t a[2][4], b[8][2];
            #pragma unroll
            for (int i = 0; i < 2; i++)
                ldsm4(a[i], sa + (uint32_t)((a_row + i * 16) * SA + ks * 8 + a_kq) * 4u);
            #pragma unroll
            for (int u = 0; u < 4; u++) {
                uint32_t r[4];
                ldsm4(r, sb + (uint32_t)((b_row + u * 16) * SA + ks * 8 + b_kq) * 4u);
                b[2 * u][0] = r[0]; b[2 * u][1] = r[1];
                b[2 * u + 1][0] = r[2]; b[2 * u + 1][1] = r[3];
            }
            #pragma unroll
            for (int i = 0; i < 2; i++)
                #pragma unroll
                for (int j = 0; j < 8; j++)
                    mma_tf32(acc[i][j], a[i], b[j]);
        }

        if ((s & 3) == 3) {     // n-tile finished: store + rezero
            int bx = s >> 2;
            float* base = g_scores + (size_t)z * SS + (size_t)m0 * SEQ + bx * 128;
            #pragma unroll
            for (int i = 0; i < 2; i++)
                #pragma unroll
                for (int j = 0; j < 8; j++) {
                    int lrow = wr * 32 + i * 16 + er;
                    int lcol = wc * 64 + j * 8 + ec;
                    *(float2*)(base + (size_t)lrow * SEQ + lcol) =
                        make_float2(acc[i][j][0], acc[i][j][1]);
                    *(float2*)(base + (size_t)(lrow + 8) * SEQ + lcol) =
                        make_float2(acc[i][j][2], acc[i][j][3]);
                    acc[i][j][0] = acc[i][j][1] = acc[i][j][2] = acc[i][j][3] = 0.0f;
                }
        }
    }
}

// ---------------------------------------------------------------------------
// causal softmax stats: per (bh,row) max m and exp-sum l. One warp per row.
// ---------------------------------------------------------------------------
__global__ __launch_bounds__(256)
void stats_causal()
{
    const int w    = threadIdx.x >> 5;
    const int lane = threadIdx.x & 31;
    const int q    = blockIdx.x * 8 + w;
    const int bh   = blockIdx.y;
    const float* row = g_scores + (size_t)bh * SS + (size_t)q * SEQ;
    const int n = q + 1;

    float m = -1e30f;
    for (int i4 = lane; i4 * 4 < n; i4 += 32) {
        float4 v = *(const float4*)(row + i4 * 4);
        int c = i4 * 4;
        if (c + 0 < n) m = fmaxf(m, v.x);
        if (c + 1 < n) m = fmaxf(m, v.y);
        if (c + 2 < n) m = fmaxf(m, v.z);
        if (c + 3 < n) m = fmaxf(m, v.w);
    }
    #pragma unroll
    for (int s = 16; s > 0; s >>= 1) m = fmaxf(m, __shfl_xor_sync(0xFFFFFFFFu, m, s));

    float l = 0.0f;
    for (int i4 = lane; i4 * 4 < n; i4 += 32) {
        float4 v = *(const float4*)(row + i4 * 4);
        int c = i4 * 4;
        if (c + 0 < n) l += __expf((v.x - m) * INVSQ);
        if (c + 1 < n) l += __expf((v.y - m) * INVSQ);
        if (c + 2 < n) l += __expf((v.z - m) * INVSQ);
        if (c + 3 < n) l += __expf((v.w - m) * INVSQ);
    }
    #pragma unroll
    for (int s = 16; s > 0; s >>= 1) l += __shfl_xor_sync(0xFFFFFFFFu, l, s);

    if (lane == 0) {
        g_m[(size_t)bh * SEQ + q] = m;
        g_l[(size_t)bh * SEQ + q] = l;
    }
}

extern "C" void kernel_launch(void* const* d_in, const int* in_sizes, int n_in,
                              void* d_out, int out_size)
{
    const float* x  = (const float*)d_in[0];
    const float* Wq = (const float*)d_in[1];
    const float* Wk = (const float*)d_in[2];
    const float* Wv = (const float*)d_in[3];
    const float* Wo = (const float*)d_in[4];
    const float* bo = (const float*)d_in[5];
    float* out = (float*)d_out;

    cudaFuncSetAttribute(gemm_tc<0>, cudaFuncAttributeMaxDynamicSharedMemorySize, SMEM_BYTES);
    cudaFuncSetAttribute(gemm_tc<2>, cudaFuncAttributeMaxDynamicSharedMemorySize, SMEM_BYTES);
    cudaFuncSetAttribute(gemm_tc<3>, cudaFuncAttributeMaxDynamicSharedMemorySize, SMEM_BYTES);
    cudaFuncSetAttribute(scores_rowpanel, cudaFuncAttributeMaxDynamicSharedMemorySize, RP_SMEM);

    dim3 blk(256);

    // fused QKV: grid.x = 48 (3 weights x 16 head tiles), raw x/W with in-loop cvt
    gemm_tc<0><<<dim3(48, 64, 1), blk, SMEM_BYTES>>>(x, Wq, Wk, Wv, nullptr, nullptr);

    // scores = Q K^T, row-panel CTAs (Q panel resident, K streamed)
    scores_rowpanel<<<dim3(16, BH), blk, RP_SMEM>>>();

    // softmax stats (max + exp-sum per row)
    stats_causal<<<dim3(SEQ / 8, BH), 256>>>();

    // ctx = softmax(S) V per (b,h); exp applied in-smem, K truncated causally
    gemm_tc<2><<<dim3(1, 16, BH), blk, SMEM_BYTES>>>(nullptr, nullptr, nullptr, nullptr, nullptr, nullptr);

    // out = ctx Wo^T + bias (raw Wo, cvt-in-loop)
    gemm_tc<3><<<dim3(16, 64, 1), blk, SMEM_BYTES>>>(nullptr, Wo, nullptr, nullptr, out, bo);
}

// round 11
// speedup vs baseline: 1.1460x; 1.1460x over previous
#include <cuda_runtime.h>
#include <cstdint>

// ---------------- problem constants ----------------
#define BATCH 4
#define SEQ 2048
#define EMB 2048
#define NH 16
#define DH 128
#define BH (BATCH * NH)          // 64
#define SD (SEQ * DH)            // 262144
#define SS ((size_t)SEQ * SEQ)
#define INVSQ 0.08838834764831845f   // 1/sqrt(128)

// scratch (allocation-free rule)
__device__ float g_q[(size_t)BH * SD];
__device__ float g_k[(size_t)BH * SD];
__device__ float g_v[(size_t)BH * SD];
__device__ float g_vt[(size_t)BH * SD];             // V transposed: [bh][n][k]
__device__ float g_scores[(size_t)BH * SS];
__device__ float g_ctx[(size_t)BATCH * SEQ * EMB];
__device__ float g_m[(size_t)BH * SEQ];             // per-row max
__device__ float g_l[(size_t)BH * SEQ];             // per-row exp-sum

__device__ __forceinline__ float rtf32(float x) {
    float y;
    asm("cvt.rna.tf32.f32 %0, %1;" : "=f"(y) : "f"(x));
    return y;
}
__device__ __forceinline__ uint32_t rtf32u(uint32_t x) {
    return __float_as_uint(rtf32(__uint_as_float(x)));
}
__device__ __forceinline__ uint32_t smem_u32(const void* p) {
    return (uint32_t)__cvta_generic_to_shared(p);
}
__device__ __forceinline__ void cp16(uint32_t s, const void* g) {
    asm volatile("cp.async.cg.shared.global [%0], [%1], 16;\n" :: "r"(s), "l"(g));
}
__device__ __forceinline__ void ldsm4(uint32_t* r, uint32_t addr) {
    asm volatile("ldmatrix.sync.aligned.m8n8.x4.shared.b16 {%0,%1,%2,%3}, [%4];"
                 : "=r"(r[0]), "=r"(r[1]), "=r"(r[2]), "=r"(r[3]) : "r"(addr));
}
__device__ __forceinline__ void mma_tf32(float* c, const uint32_t* a, const uint32_t* b) {
    asm volatile(
        "mma.sync.aligned.m16n8k8.row.col.f32.tf32.tf32.f32 "
        "{%0,%1,%2,%3},{%4,%5,%6,%7},{%8,%9},{%0,%1,%2,%3};"
        : "+f"(c[0]), "+f"(c[1]), "+f"(c[2]), "+f"(c[3])
        : "r"(a[0]), "r"(a[1]), "r"(a[2]), "r"(a[3]), "r"(b[0]), "r"(b[1]));
}

// ---------------------------------------------------------------------------
// TF32 mma.sync GEMM, CTA 128x128, 256 threads = 8 warps (4m x 2n),
// warp tile 32x64, BK=32, 3-stage cp.async pipeline, ldmatrix operand loads.
// MODE 0: fused QKV proj; grid.x=48: sel=bx>>4 picks Wq/Wk/Wv, head=bx&15.
//         raw fp32 inputs, cvt to tf32 in-register. Rounded scatter out.
// MODE 1: scores = Q K^T per (b,h), raw out; blocks above diagonal skipped.
// MODE 2: ctx = softmax(S) V per (b,h); exp+mask fused into A fragments
//         (stats g_m/g_l in regs), B from pre-transposed g_vt, K truncated.
// MODE 3: out proj C = ctx * Wo^T + bias (B raw, cvt-in-loop).
// ---------------------------------------------------------------------------
#define BK 32
#define SA 36                                  // tile row stride in floats
#define B_OFF (128 * SA)                       // words
#define STAGE_WORDS (2 * 128 * SA)             // 9216 words
#define NSTAGE 3
#define SMEM_BYTES (NSTAGE * STAGE_WORDS * 4)  // 110592

template<int MODE>
__global__ __launch_bounds__(256, 2)
void gemm_tc(const float* __restrict__ Aext, const float* __restrict__ Bq,
             const float* __restrict__ Bk, const float* __restrict__ Bv,
             float* __restrict__ Oext, const float* __restrict__ bias)
{
    if (MODE == 1 && blockIdx.x > blockIdx.y) return;   // fully-masked causal block

    extern __shared__ float dyn[];

    const int tid  = threadIdx.x;
    const int wid  = tid >> 5;
    const int lane = tid & 31;
    const int wr   = wid >> 1;     // 4 m-groups of 32
    const int wc   = wid & 1;      // 2 n-groups of 64
    const int lq   = lane >> 3;
    const int lr   = lane & 7;
    const int m0   = blockIdx.y * 128;
    const int z    = blockIdx.z;
    const int sel  = (MODE == 0) ? (blockIdx.x >> 4) : 0;
    const int n0   = (MODE == 0) ? (blockIdx.x & 15) * 128 : blockIdx.x * 128;

    const float* A;  int lda;
    const float* Bm; int ldb;
    int Ktot;
    if (MODE == 0)      { A = Aext;                      lda = EMB;
                          Bm = (sel == 0 ? Bq : sel == 1 ? Bk : Bv); ldb = EMB; Ktot = EMB; }
    else if (MODE == 1) { A = g_q + (size_t)z * SD;      lda = DH;  Bm = g_k + (size_t)z * SD;  ldb = DH;  Ktot = DH; }
    else if (MODE == 2) { A = g_scores + (size_t)z * SS; lda = SEQ; Bm = g_vt + (size_t)z * SD; ldb = SEQ; Ktot = m0 + 128; }
    else                { A = g_ctx;                     lda = EMB; Bm = Bq;                    ldb = EMB; Ktot = EMB; }
    const int T = Ktot / BK;

    const uint32_t sbase = smem_u32(dyn);

    // MODE2: per-thread softmax stats for the 4 fragment rows this thread owns
    float mst[4], rlst[4];
    int grow0 = 0;
    if (MODE == 2) {
        grow0 = m0 + wr * 32 + (lane >> 2);     // rows grow0 + {0,8,16,24}
        #pragma unroll
        for (int u = 0; u < 4; u++) {
            int r = grow0 + u * 8;
            mst[u]  = g_m[(size_t)z * SEQ + r];
            rlst[u] = 1.0f / g_l[(size_t)z * SEQ + r];
        }
    }

    auto load_stage = [&](int buf, int t) {
        const int k0 = t * BK;
        const uint32_t sa = sbase + (uint32_t)(buf * STAGE_WORDS) * 4u;
        #pragma unroll
        for (int i = 0; i < 4; i++) {
            int id = tid + i * 256;
            int r = id >> 3, c4 = id & 7;
            cp16(sa + (uint32_t)(r * SA + c4 * 4) * 4u,
                 A + (size_t)(m0 + r) * lda + k0 + c4 * 4);
        }
        #pragma unroll
        for (int i = 0; i < 4; i++) {
            int id = tid + i * 256;
            int r = id >> 3, c4 = id & 7;
            cp16(sa + (uint32_t)(B_OFF + r * SA + c4 * 4) * 4u,
                 Bm + (size_t)(n0 + r) * ldb + k0 + c4 * 4);
        }
        asm volatile("cp.async.commit_group;\n");
    };

    float acc[2][8][4];
    #pragma unroll
    for (int i = 0; i < 2; i++)
        #pragma unroll
        for (int j = 0; j < 8; j++)
            #pragma unroll
            for (int e = 0; e < 4; e++) acc[i][j][e] = 0.0f;

    load_stage(0, 0);
    load_stage(1, 1);

    const int a_row = wr * 32 + (lq & 1) * 8 + lr;
    const int a_kq  = (lq >> 1) * 4;
    const int b_row = wc * 64 + (lq >> 1) * 8 + lr;
    const int b_kq  = (lq & 1) * 4;

    for (int t = 0; t < T; t++) {
        asm volatile("cp.async.wait_group 1;\n" ::: "memory");
        __syncthreads();

        if (t + 2 < T) load_stage((t + 2) % NSTAGE, t + 2);
        else asm volatile("cp.async.commit_group;\n");

        const uint32_t st = sbase + (uint32_t)((t % NSTAGE) * STAGE_WORDS) * 4u;

        #pragma unroll
        for (int ks = 0; ks < 4; ks++) {
            uint32_t a[2][4], b[8][2];
            #pragma unroll
            for (int i = 0; i < 2; i++)
                ldsm4(a[i], st + (uint32_t)((a_row + i * 16) * SA + ks * 8 + a_kq) * 4u);
            #pragma unroll
            for (int u = 0; u < 4; u++) {
                uint32_t r[4];
                ldsm4(r, st + (uint32_t)(B_OFF + (b_row + u * 16) * SA + ks * 8 + b_kq) * 4u);
                b[2 * u][0] = r[0]; b[2 * u][1] = r[1];
                b[2 * u + 1][0] = r[2]; b[2 * u + 1][1] = r[3];
            }
            if (MODE == 0) {   // raw x -> tf32
                #pragma unroll
                for (int i = 0; i < 2; i++)
                    #pragma unroll
                    for (int e = 0; e < 4; e++) a[i][e] = rtf32u(a[i][e]);
            }
            if (MODE == 0 || MODE == 3) {   // raw W -> tf32
                #pragma unroll
                for (int j = 0; j < 8; j++) {
                    b[j][0] = rtf32u(b[j][0]); b[j][1] = rtf32u(b[j][1]);
                }
            }
            if (MODE == 2) {   // fuse softmax exp + causal mask into A fragments
                const int kb = t * 32 + ks * 8 + (lane & 3);
                #pragma unroll
                for (int i = 0; i < 2; i++)
                    #pragma unroll
                    for (int e = 0; e < 4; e++) {
                        const int u  = i * 2 + (e & 1);          // stat slot
                        const int kg = kb + (e >> 1) * 4;        // global k index
                        const int gr = grow0 + u * 8;            // global row
                        float s = __uint_as_float(a[i][e]);
                        float p = (kg <= gr)
                            ? rtf32(__expf((s - mst[u]) * INVSQ) * rlst[u]) : 0.0f;
                        a[i][e] = __float_as_uint(p);
                    }
            }
            #pragma unroll
            for (int i = 0; i < 2; i++)
                #pragma unroll
                for (int j = 0; j < 8; j++)
                    mma_tf32(acc[i][j], a[i], b[j]);
        }
    }

    // ---- epilogue ----
    float* base; size_t ldo;
    bool do_round;
    if (MODE == 0) {
        int b = m0 >> 11;
        float* qkv = (sel == 0 ? g_q : sel == 1 ? g_k : g_v);
        base = qkv + ((size_t)(b * NH + (blockIdx.x & 15))) * SD + (size_t)(m0 & (SEQ - 1)) * DH;
        ldo = DH;  do_round = true;
    } else if (MODE == 1) {
        base = g_scores + (size_t)z * SS + (size_t)m0 * SEQ + n0;
        ldo = SEQ; do_round = false;
    } else if (MODE == 2) {
        int b = z >> 4, h = z & 15;
        base = g_ctx + (size_t)b * SEQ * EMB + (size_t)m0 * EMB + h * DH;
        ldo = EMB; do_round = true;
    } else {
        base = Oext + (size_t)m0 * EMB + n0;
        ldo = EMB; do_round = false;
    }

    const int er = lane >> 2;
    const int ec = (lane & 3) * 2;
    #pragma unroll
    for (int i = 0; i < 2; i++)
        #pragma unroll
        for (int j = 0; j < 8; j++) {
            int lrow = wr * 32 + i * 16 + er;
            int lcol = wc * 64 + j * 8 + ec;
            float2 v0, v1;
            if (do_round) {
                v0 = make_float2(rtf32(acc[i][j][0]), rtf32(acc[i][j][1]));
                v1 = make_float2(rtf32(acc[i][j][2]), rtf32(acc[i][j][3]));
            } else {
                v0 = make_float2(acc[i][j][0], acc[i][j][1]);
                v1 = make_float2(acc[i][j][2], acc[i][j][3]);
            }
            if (MODE == 3) {
                float b0 = bias[n0 + lcol], b1 = bias[n0 + lcol + 1];
                v0.x += b0; v0.y += b1; v1.x += b0; v1.y += b1;
            }
            *(float2*)(base + (size_t)lrow * ldo + lcol) = v0;
            *(float2*)(base + (size_t)(lrow + 8) * ldo + lcol) = v1;
        }
}

// ---------------------------------------------------------------------------
// V transpose: g_v [bh][k][n] -> g_vt [bh][n][k], 32x32 smem tiles
// ---------------------------------------------------------------------------
__global__ __launch_bounds__(256)
void transpose_v()
{
    __shared__ float tile[32][33];
    const int z  = blockIdx.z;
    const int k0 = blockIdx.x * 32;
    const int n0 = blockIdx.y * 32;
    const int tx = threadIdx.x & 31;
    const int ty = threadIdx.x >> 5;      // 8 rows per pass

    const float* src = g_v + (size_t)z * SD;
    #pragma unroll
    for (int j = 0; j < 4; j++)
        tile[ty + j * 8][tx] = src[(size_t)(k0 + ty + j * 8) * DH + n0 + tx];
    __syncthreads();
    float* dst = g_vt + (size_t)z * SD;
    #pragma unroll
    for (int j = 0; j < 4; j++)
        dst[(size_t)(n0 + ty + j * 8) * SEQ + k0 + tx] = tile[tx][ty + j * 8];
}

// ---------------------------------------------------------------------------
// causal softmax stats: per (bh,row) max m and exp-sum l. One warp per row.
// ---------------------------------------------------------------------------
__global__ __launch_bounds__(256)
void stats_causal()
{
    const int w    = threadIdx.x >> 5;
    const int lane = threadIdx.x & 31;
    const int q    = blockIdx.x * 8 + w;
    const int bh   = blockIdx.y;
    const float* row = g_scores + (size_t)bh * SS + (size_t)q * SEQ;
    const int n = q + 1;

    float m = -1e30f;
    for (int i4 = lane; i4 * 4 < n; i4 += 32) {
        float4 v = *(const float4*)(row + i4 * 4);
        int c = i4 * 4;
        if (c + 0 < n) m = fmaxf(m, v.x);
        if (c + 1 < n) m = fmaxf(m, v.y);
        if (c + 2 < n) m = fmaxf(m, v.z);
        if (c + 3 < n) m = fmaxf(m, v.w);
    }
    #pragma unroll
    for (int s = 16; s > 0; s >>= 1) m = fmaxf(m, __shfl_xor_sync(0xFFFFFFFFu, m, s));

    float l = 0.0f;
    for (int i4 = lane; i4 * 4 < n; i4 += 32) {
        float4 v = *(const float4*)(row + i4 * 4);
        int c = i4 * 4;
        if (c + 0 < n) l += __expf((v.x - m) * INVSQ);
        if (c + 1 < n) l += __expf((v.y - m) * INVSQ);
        if (c + 2 < n) l += __expf((v.z - m) * INVSQ);
        if (c + 3 < n) l += __expf((v.w - m) * INVSQ);
    }
    #pragma unroll
    for (int s = 16; s > 0; s >>= 1) l += __shfl_xor_sync(0xFFFFFFFFu, l, s);

    if (lane == 0) {
        g_m[(size_t)bh * SEQ + q] = m;
        g_l[(size_t)bh * SEQ + q] = l;
    }
}

extern "C" void kernel_launch(void* const* d_in, const int* in_sizes, int n_in,
                              void* d_out, int out_size)
{
    const float* x  = (const float*)d_in[0];
    const float* Wq = (const float*)d_in[1];
    const float* Wk = (const float*)d_in[2];
    const float* Wv = (const float*)d_in[3];
    const float* Wo = (const float*)d_in[4];
    const float* bo = (const float*)d_in[5];
    float* out = (float*)d_out;

    cudaFuncSetAttribute(gemm_tc<0>, cudaFuncAttributeMaxDynamicSharedMemorySize, SMEM_BYTES);
    cudaFuncSetAttribute(gemm_tc<1>, cudaFuncAttributeMaxDynamicSharedMemorySize, SMEM_BYTES);
    cudaFuncSetAttribute(gemm_tc<2>, cudaFuncAttributeMaxDynamicSharedMemorySize, SMEM_BYTES);
    cudaFuncSetAttribute(gemm_tc<3>, cudaFuncAttributeMaxDynamicSharedMemorySize, SMEM_BYTES);

    dim3 blk(256);

    // fused QKV: grid.x = 48 (3 weights x 16 head tiles), in-loop tf32 cvt
    gemm_tc<0><<<dim3(48, 64, 1), blk, SMEM_BYTES>>>(x, Wq, Wk, Wv, nullptr, nullptr);

    // V transpose for MODE2's B operand
    transpose_v<<<dim3(SEQ / 32, DH / 32, BH), blk>>>();

    // scores = Q K^T per (b,h), raw; above-diagonal blocks skipped
    gemm_tc<1><<<dim3(16, 16, BH), blk, SMEM_BYTES>>>(nullptr, nullptr, nullptr, nullptr, nullptr, nullptr);

    // softmax stats (max + exp-sum per row)
    stats_causal<<<dim3(SEQ / 8, BH), 256>>>();

    // ctx = softmax(S) V per (b,h); exp fused into A fragments
    gemm_tc<2><<<dim3(1, 16, BH), blk, SMEM_BYTES>>>(nullptr, nullptr, nullptr, nullptr, nullptr, nullptr);

    // out = ctx Wo^T + bias (raw Wo, cvt-in-loop)
    gemm_tc<3><<<dim3(16, 64, 1), blk, SMEM_BYTES>>>(nullptr, Wo, nullptr, nullptr, out, bo);
}

// round 12
// speedup vs baseline: 1.1662x; 1.0176x over previous
#include <cuda_runtime.h>
#include <cstdint>

// ---------------- problem constants ----------------
#define BATCH 4
#define SEQ 2048
#define EMB 2048
#define NH 16
#define DH 128
#define BH (BATCH * NH)          // 64
#define SD (SEQ * DH)            // 262144
#define SS ((size_t)SEQ * SEQ)
#define INVSQ 0.08838834764831845f   // 1/sqrt(128)

// scratch (allocation-free rule)
__device__ float g_q[(size_t)BH * SD];
__device__ float g_k[(size_t)BH * SD];
__device__ float g_v[(size_t)BH * SD];
__device__ float g_vt[(size_t)BH * SD];             // V transposed: [bh][n][k]
__device__ float g_scores[(size_t)BH * SS];
__device__ float g_ctx[(size_t)BATCH * SEQ * EMB];
__device__ float g_m[(size_t)BH * SEQ];             // per-row max
__device__ float g_l[(size_t)BH * SEQ];             // per-row exp-sum
__device__ float g_pm[(size_t)BH * 16 * SEQ];       // per-block row max
__device__ float g_pl[(size_t)BH * 16 * SEQ];       // per-block row exp-sum

__device__ __forceinline__ float rtf32(float x) {
    float y;
    asm("cvt.rna.tf32.f32 %0, %1;" : "=f"(y) : "f"(x));
    return y;
}
__device__ __forceinline__ uint32_t rtf32u(uint32_t x) {
    return __float_as_uint(rtf32(__uint_as_float(x)));
}
__device__ __forceinline__ uint32_t smem_u32(const void* p) {
    return (uint32_t)__cvta_generic_to_shared(p);
}
__device__ __forceinline__ void cp16(uint32_t s, const void* g) {
    asm volatile("cp.async.cg.shared.global [%0], [%1], 16;\n" :: "r"(s), "l"(g));
}
__device__ __forceinline__ void ldsm4(uint32_t* r, uint32_t addr) {
    asm volatile("ldmatrix.sync.aligned.m8n8.x4.shared.b16 {%0,%1,%2,%3}, [%4];"
                 : "=r"(r[0]), "=r"(r[1]), "=r"(r[2]), "=r"(r[3]) : "r"(addr));
}
__device__ __forceinline__ void mma_tf32(float* c, const uint32_t* a, const uint32_t* b) {
    asm volatile(
        "mma.sync.aligned.m16n8k8.row.col.f32.tf32.tf32.f32 "
        "{%0,%1,%2,%3},{%4,%5,%6,%7},{%8,%9},{%0,%1,%2,%3};"
        : "+f"(c[0]), "+f"(c[1]), "+f"(c[2]), "+f"(c[3])
        : "r"(a[0]), "r"(a[1]), "r"(a[2]), "r"(a[3]), "r"(b[0]), "r"(b[1]));
}

// ---------------------------------------------------------------------------
// TF32 mma.sync GEMM, CTA 128x128, 256 threads = 8 warps (4m x 2n),
// warp tile 32x64, BK=32, 3-stage cp.async pipeline, ldmatrix operand loads.
// MODE 0: fused QKV proj; grid.x=48: sel=bx>>4 picks Wq/Wk/Wv, head=bx&15.
// MODE 1: scores = Q K^T per (b,h), raw out + per-block softmax partials
//         (pm, pl) computed in the epilogue; above-diagonal blocks skipped.
// MODE 2: ctx = softmax(S) V per (b,h); exp+mask fused into A fragments
//         (stats g_m/g_l in regs), B from pre-transposed g_vt, K truncated.
// MODE 3: out proj C = ctx * Wo^T + bias (B raw, cvt-in-loop).
// ---------------------------------------------------------------------------
#define BK 32
#define SA 36                                  // tile row stride in floats
#define B_OFF (128 * SA)                       // words
#define STAGE_WORDS (2 * 128 * SA)             // 9216 words
#define NSTAGE 3
#define SMEM_BYTES (NSTAGE * STAGE_WORDS * 4)  // 110592

template<int MODE>
__global__ __launch_bounds__(256, 2)
void gemm_tc(const float* __restrict__ Aext, const float* __restrict__ Bq,
             const float* __restrict__ Bk, const float* __restrict__ Bv,
             float* __restrict__ Oext, const float* __restrict__ bias)
{
    if (MODE == 1 && blockIdx.x > blockIdx.y) return;   // fully-masked causal block

    extern __shared__ float dyn[];

    const int tid  = threadIdx.x;
    const int wid  = tid >> 5;
    const int lane = tid & 31;
    const int wr   = wid >> 1;     // 4 m-groups of 32
    const int wc   = wid & 1;      // 2 n-groups of 64
    const int lq   = lane >> 3;
    const int lr   = lane & 7;
    const int m0   = blockIdx.y * 128;
    const int z    = blockIdx.z;
    const int sel  = (MODE == 0) ? (blockIdx.x >> 4) : 0;
    const int n0   = (MODE == 0) ? (blockIdx.x & 15) * 128 : blockIdx.x * 128;

    const float* A;  int lda;
    const float* Bm; int ldb;
    int Ktot;
    if (MODE == 0)      { A = Aext;                      lda = EMB;
                          Bm = (sel == 0 ? Bq : sel == 1 ? Bk : Bv); ldb = EMB; Ktot = EMB; }
    else if (MODE == 1) { A = g_q + (size_t)z * SD;      lda = DH;  Bm = g_k + (size_t)z * SD;  ldb = DH;  Ktot = DH; }
    else if (MODE == 2) { A = g_scores + (size_t)z * SS; lda = SEQ; Bm = g_vt + (size_t)z * SD; ldb = SEQ; Ktot = m0 + 128; }
    else                { A = g_ctx;                     lda = EMB; Bm = Bq;                    ldb = EMB; Ktot = EMB; }
    const int T = Ktot / BK;

    const uint32_t sbase = smem_u32(dyn);

    // MODE2: per-thread softmax stats for the 4 fragment rows this thread owns
    float mst[4], rlst[4];
    int grow0 = 0;
    if (MODE == 2) {
        grow0 = m0 + wr * 32 + (lane >> 2);     // rows grow0 + {0,8,16,24}
        #pragma unroll
        for (int u = 0; u < 4; u++) {
            int r = grow0 + u * 8;
            mst[u]  = g_m[(size_t)z * SEQ + r];
            rlst[u] = 1.0f / g_l[(size_t)z * SEQ + r];
        }
    }

    auto load_stage = [&](int buf, int t) {
        const int k0 = t * BK;
        const uint32_t sa = sbase + (uint32_t)(buf * STAGE_WORDS) * 4u;
        #pragma unroll
        for (int i = 0; i < 4; i++) {
            int id = tid + i * 256;
            int r = id >> 3, c4 = id & 7;
            cp16(sa + (uint32_t)(r * SA + c4 * 4) * 4u,
                 A + (size_t)(m0 + r) * lda + k0 + c4 * 4);
        }
        #pragma unroll
        for (int i = 0; i < 4; i++) {
            int id = tid + i * 256;
            int r = id >> 3, c4 = id & 7;
            cp16(sa + (uint32_t)(B_OFF + r * SA + c4 * 4) * 4u,
                 Bm + (size_t)(n0 + r) * ldb + k0 + c4 * 4);
        }
        asm volatile("cp.async.commit_group;\n");
    };

    float acc[2][8][4];
    #pragma unroll
    for (int i = 0; i < 2; i++)
        #pragma unroll
        for (int j = 0; j < 8; j++)
            #pragma unroll
            for (int e = 0; e < 4; e++) acc[i][j][e] = 0.0f;

    load_stage(0, 0);
    load_stage(1, 1);

    const int a_row = wr * 32 + (lq & 1) * 8 + lr;
    const int a_kq  = (lq >> 1) * 4;
    const int b_row = wc * 64 + (lq >> 1) * 8 + lr;
    const int b_kq  = (lq & 1) * 4;

    for (int t = 0; t < T; t++) {
        asm volatile("cp.async.wait_group 1;\n" ::: "memory");
        __syncthreads();

        if (t + 2 < T) load_stage((t + 2) % NSTAGE, t + 2);
        else asm volatile("cp.async.commit_group;\n");

        const uint32_t st = sbase + (uint32_t)((t % NSTAGE) * STAGE_WORDS) * 4u;

        #pragma unroll
        for (int ks = 0; ks < 4; ks++) {
            uint32_t a[2][4], b[8][2];
            #pragma unroll
            for (int i = 0; i < 2; i++)
                ldsm4(a[i], st + (uint32_t)((a_row + i * 16) * SA + ks * 8 + a_kq) * 4u);
            #pragma unroll
            for (int u = 0; u < 4; u++) {
                uint32_t r[4];
                ldsm4(r, st + (uint32_t)(B_OFF + (b_row + u * 16) * SA + ks * 8 + b_kq) * 4u);
                b[2 * u][0] = r[0]; b[2 * u][1] = r[1];
                b[2 * u + 1][0] = r[2]; b[2 * u + 1][1] = r[3];
            }
            if (MODE == 0) {   // raw x -> tf32
                #pragma unroll
                for (int i = 0; i < 2; i++)
                    #pragma unroll
                    for (int e = 0; e < 4; e++) a[i][e] = rtf32u(a[i][e]);
            }
            if (MODE == 0 || MODE == 3) {   // raw W -> tf32
                #pragma unroll
                for (int j = 0; j < 8; j++) {
                    b[j][0] = rtf32u(b[j][0]); b[j][1] = rtf32u(b[j][1]);
                }
            }
            if (MODE == 2) {   // fuse softmax exp + causal mask into A fragments
                const int kb = t * 32 + ks * 8 + (lane & 3);
                #pragma unroll
                for (int i = 0; i < 2; i++)
                    #pragma unroll
                    for (int e = 0; e < 4; e++) {
                        const int u  = i * 2 + (e & 1);          // stat slot
                        const int kg = kb + (e >> 1) * 4;        // global k index
                        const int gr = grow0 + u * 8;            // global row
                        float s = __uint_as_float(a[i][e]);
                        float p = (kg <= gr)
                            ? rtf32(__expf((s - mst[u]) * INVSQ) * rlst[u]) : 0.0f;
                        a[i][e] = __float_as_uint(p);
                    }
            }
            #pragma unroll
            for (int i = 0; i < 2; i++)
                #pragma unroll
                for (int j = 0; j < 8; j++)
                    mma_tf32(acc[i][j], a[i], b[j]);
        }
    }

    // ---- epilogue ----
    float* base; size_t ldo;
    bool do_round;
    if (MODE == 0) {
        int b = m0 >> 11;
        float* qkv = (sel == 0 ? g_q : sel == 1 ? g_k : g_v);
        base = qkv + ((size_t)(b * NH + (blockIdx.x & 15))) * SD + (size_t)(m0 & (SEQ - 1)) * DH;
        ldo = DH;  do_round = true;
    } else if (MODE == 1) {
        base = g_scores + (size_t)z * SS + (size_t)m0 * SEQ + n0;
        ldo = SEQ; do_round = false;
    } else if (MODE == 2) {
        int b = z >> 4, h = z & 15;
        base = g_ctx + (size_t)b * SEQ * EMB + (size_t)m0 * EMB + h * DH;
        ldo = EMB; do_round = true;
    } else {
        base = Oext + (size_t)m0 * EMB + n0;
        ldo = EMB; do_round = false;
    }

    const int er = lane >> 2;
    const int ec = (lane & 3) * 2;
    #pragma unroll
    for (int i = 0; i < 2; i++)
        #pragma unroll
        for (int j = 0; j < 8; j++) {
            int lrow = wr * 32 + i * 16 + er;
            int lcol = wc * 64 + j * 8 + ec;
            float2 v0, v1;
            if (do_round) {
                v0 = make_float2(rtf32(acc[i][j][0]), rtf32(acc[i][j][1]));
                v1 = make_float2(rtf32(acc[i][j][2]), rtf32(acc[i][j][3]));
            } else {
                v0 = make_float2(acc[i][j][0], acc[i][j][1]);
                v1 = make_float2(acc[i][j][2], acc[i][j][3]);
            }
            if (MODE == 3) {
                float b0 = bias[n0 + lcol], b1 = bias[n0 + lcol + 1];
                v0.x += b0; v0.y += b1; v1.x += b0; v1.y += b1;
            }
            *(float2*)(base + (size_t)lrow * ldo + lcol) = v0;
            *(float2*)(base + (size_t)(lrow + 8) * ldo + lcol) = v1;
        }

    // ---- MODE1: per-block softmax partials (pm, pl) from registers ----
    if (MODE == 1) {
        __syncthreads();                         // pipeline smem is dead; reuse as scratch
        float* sm_m = dyn;                       // [8 warps][32 rows]
        float* sm_l = dyn + 256;

        #pragma unroll
        for (int i = 0; i < 2; i++)
            #pragma unroll
            for (int h = 0; h < 2; h++) {
                const int lrow = wr * 32 + i * 16 + er + h * 8;
                const int grow = m0 + lrow;
                float mx = -1e30f;
                #pragma unroll
                for (int j = 0; j < 8; j++) {
                    int c0 = n0 + wc * 64 + j * 8 + ec;
                    float x0 = (c0     <= grow) ? acc[i][j][h * 2]     : -1e30f;
                    float x1 = (c0 + 1 <= grow) ? acc[i][j][h * 2 + 1] : -1e30f;
                    mx = fmaxf(mx, fmaxf(x0, x1));
                }
                mx = fmaxf(mx, __shfl_xor_sync(0xFFFFFFFFu, mx, 1));
                mx = fmaxf(mx, __shfl_xor_sync(0xFFFFFFFFu, mx, 2));
                float sum = 0.0f;
                #pragma unroll
                for (int j = 0; j < 8; j++) {
                    int c0 = n0 + wc * 64 + j * 8 + ec;
                    if (c0     <= grow) sum += __expf((acc[i][j][h * 2]     - mx) * INVSQ);
                    if (c0 + 1 <= grow) sum += __expf((acc[i][j][h * 2 + 1] - mx) * INVSQ);
                }
                sum += __shfl_xor_sync(0xFFFFFFFFu, sum, 1);
                sum += __shfl_xor_sync(0xFFFFFFFFu, sum, 2);
                if ((lane & 3) == 0) {
                    int rl32 = i * 16 + er + h * 8;     // 0..31 within warp's rows
                    sm_m[wid * 32 + rl32] = mx;
                    sm_l[wid * 32 + rl32] = sum;
                }
            }
        __syncthreads();
        if (tid < 128) {
            int r = tid, wrg = r >> 5, rl32 = r & 31;
            float ma = sm_m[(wrg * 2) * 32 + rl32];
            float mb = sm_m[(wrg * 2 + 1) * 32 + rl32];
            float mm = fmaxf(ma, mb);
            float ll = __expf((ma - mm) * INVSQ) * sm_l[(wrg * 2) * 32 + rl32]
                     + __expf((mb - mm) * INVSQ) * sm_l[(wrg * 2 + 1) * 32 + rl32];
            size_t off = ((size_t)z * 16 + blockIdx.x) * SEQ + m0 + r;
            g_pm[off] = mm;
            g_pl[off] = ll;
        }
    }
}

// ---------------------------------------------------------------------------
// combine per-block partials into per-row softmax stats (m, l)
// ---------------------------------------------------------------------------
__global__ __launch_bounds__(256)
void combine_stats()
{
    int idx = blockIdx.x * 256 + threadIdx.x;   // 0 .. BH*SEQ-1
    int z = idx >> 11;
    int q = idx & (SEQ - 1);
    int nb = (q >> 7) + 1;

    float m = -1e30f;
    for (int b = 0; b < nb; b++)
        m = fmaxf(m, g_pm[((size_t)z * 16 + b) * SEQ + q]);
    float l = 0.0f;
    for (int b = 0; b < nb; b++) {
        size_t off = ((size_t)z * 16 + b) * SEQ + q;
        l += __expf((g_pm[off] - m) * INVSQ) * g_pl[off];
    }
    g_m[(size_t)z * SEQ + q] = m;
    g_l[(size_t)z * SEQ + q] = l;
}

// ---------------------------------------------------------------------------
// V transpose: g_v [bh][k][n] -> g_vt [bh][n][k], 32x32 smem tiles
// ---------------------------------------------------------------------------
__global__ __launch_bounds__(256)
void transpose_v()
{
    __shared__ float tile[32][33];
    const int z  = blockIdx.z;
    const int k0 = blockIdx.x * 32;
    const int n0 = blockIdx.y * 32;
    const int tx = threadIdx.x & 31;
    const int ty = threadIdx.x >> 5;      // 8 rows per pass

    const float* src = g_v + (size_t)z * SD;
    #pragma unroll
    for (int j = 0; j < 4; j++)
        tile[ty + j * 8][tx] = src[(size_t)(k0 + ty + j * 8) * DH + n0 + tx];
    __syncthreads();
    float* dst = g_vt + (size_t)z * SD;
    #pragma unroll
    for (int j = 0; j < 4; j++)
        dst[(size_t)(n0 + ty + j * 8) * SEQ + k0 + tx] = tile[tx][ty + j * 8];
}

extern "C" void kernel_launch(void* const* d_in, const int* in_sizes, int n_in,
                              void* d_out, int out_size)
{
    const float* x  = (const float*)d_in[0];
    const float* Wq = (const float*)d_in[1];
    const float* Wk = (const float*)d_in[2];
    const float* Wv = (const float*)d_in[3];
    const float* Wo = (const float*)d_in[4];
    const float* bo = (const float*)d_in[5];
    float* out = (float*)d_out;

    cudaFuncSetAttribute(gemm_tc<0>, cudaFuncAttributeMaxDynamicSharedMemorySize, SMEM_BYTES);
    cudaFuncSetAttribute(gemm_tc<1>, cudaFuncAttributeMaxDynamicSharedMemorySize, SMEM_BYTES);
    cudaFuncSetAttribute(gemm_tc<2>, cudaFuncAttributeMaxDynamicSharedMemorySize, SMEM_BYTES);
    cudaFuncSetAttribute(gemm_tc<3>, cudaFuncAttributeMaxDynamicSharedMemorySize, SMEM_BYTES);

    dim3 blk(256);

    // fused QKV: grid.x = 48 (3 weights x 16 head tiles), in-loop tf32 cvt
    gemm_tc<0><<<dim3(48, 64, 1), blk, SMEM_BYTES>>>(x, Wq, Wk, Wv, nullptr, nullptr);

    // V transpose for MODE2's B operand
    transpose_v<<<dim3(SEQ / 32, DH / 32, BH), blk>>>();

    // scores = Q K^T per (b,h) + in-epilogue softmax partials
    gemm_tc<1><<<dim3(16, 16, BH), blk, SMEM_BYTES>>>(nullptr, nullptr, nullptr, nullptr, nullptr, nullptr);

    // combine partials -> per-row (m, l)
    combine_stats<<<BH * SEQ / 256, 256>>>();

    // ctx = softmax(S) V per (b,h); exp fused into A fragments
    gemm_tc<2><<<dim3(1, 16, BH), blk, SMEM_BYTES>>>(nullptr, nullptr, nullptr, nullptr, nullptr, nullptr);

    // out = ctx Wo^T + bias (raw Wo, cvt-in-loop)
    gemm_tc<3><<<dim3(16, 64, 1), blk, SMEM_BYTES>>>(nullptr, Wo, nullptr, nullptr, out, bo);
}

// round 13
// speedup vs baseline: 1.9508x; 1.6728x over previous
#include <cuda_runtime.h>
#include <cuda_fp16.h>
#include <cstdint>

// ---------------- problem constants ----------------
#define BATCH 4
#define SEQ 2048
#define EMB 2048
#define NH 16
#define DH 128
#define BH (BATCH * NH)          // 64
#define SD (SEQ * DH)            // 262144
#define SS ((size_t)SEQ * SEQ)
#define INVSQ 0.08838834764831845f   // 1/sqrt(128)

// scratch (allocation-free rule) — all fp16 except stats
__device__ __half g_xh[(size_t)BATCH * SEQ * EMB];
__device__ __half g_wh[4][(size_t)EMB * EMB];
__device__ __half g_qh[(size_t)BH * SD];
__device__ __half g_kh[(size_t)BH * SD];
__device__ __half g_vh[(size_t)BH * SD];
__device__ __half g_vth[(size_t)BH * SD];           // V transposed: [bh][dh][seq]
__device__ __half g_sh[(size_t)BH * SS];            // raw scores
__device__ __half g_ctxh[(size_t)BATCH * SEQ * EMB];
__device__ float g_m[(size_t)BH * SEQ];
__device__ float g_l[(size_t)BH * SEQ];
__device__ float g_pm[(size_t)BH * 16 * SEQ];
__device__ float g_pl[(size_t)BH * 16 * SEQ];

__device__ __forceinline__ uint32_t smem_u32(const void* p) {
    return (uint32_t)__cvta_generic_to_shared(p);
}
__device__ __forceinline__ void cp16(uint32_t s, const void* g) {
    asm volatile("cp.async.cg.shared.global [%0], [%1], 16;\n" :: "r"(s), "l"(g));
}
__device__ __forceinline__ void ldsm4(uint32_t* r, uint32_t addr) {
    asm volatile("ldmatrix.sync.aligned.m8n8.x4.shared.b16 {%0,%1,%2,%3}, [%4];"
                 : "=r"(r[0]), "=r"(r[1]), "=r"(r[2]), "=r"(r[3]) : "r"(addr));
}
__device__ __forceinline__ void mma_f16(float* c, const uint32_t* a, const uint32_t* b) {
    asm volatile(
        "mma.sync.aligned.m16n8k16.row.col.f32.f16.f16.f32 "
        "{%0,%1,%2,%3},{%4,%5,%6,%7},{%8,%9},{%0,%1,%2,%3};"
        : "+f"(c[0]), "+f"(c[1]), "+f"(c[2]), "+f"(c[3])
        : "r"(a[0]), "r"(a[1]), "r"(a[2]), "r"(a[3]), "r"(b[0]), "r"(b[1]));
}

// ---------------------------------------------------------------------------
// FP16 mma.sync GEMM (fp32 accum), CTA 128x128, 256 threads = 8 warps (4m x 2n),
// warp tile 32x64, BK=32, 3-stage cp.async pipeline, ldmatrix operands.
// Smem tiles fp16 K-contiguous [row][k], stride 40 halves (80B: 16B-aligned,
// conflict-free ldmatrix).
// MODE 0: fused QKV proj; grid.x=48: sel=bx>>4 picks Wq/Wk/Wv, head=bx&15.
// MODE 1: scores = Q K^T per (b,h), fp16 out + per-block softmax partials
//         in epilogue; above-diagonal blocks skipped.
// MODE 2: ctx = softmax(S) V per (b,h); exp+mask fused into A fragments,
//         B = pre-transposed g_vth, K truncated causally.
// MODE 3: out proj C = ctx * Wo^T + bias, fp32 out.
// ---------------------------------------------------------------------------
#define BK 32
#define SA_H 40                                 // tile row stride (halves)
#define B_OFF_H (128 * SA_H)                    // halves
#define STAGE_H (2 * 128 * SA_H)                // 10240 halves = 20480 B
#define NSTAGE 3
#define SMEM_BYTES (NSTAGE * STAGE_H * 2)       // 61440

template<int MODE>
__global__ __launch_bounds__(256, 2)
void gemm_tc(float* __restrict__ Oext, const float* __restrict__ bias)
{
    if (MODE == 1 && blockIdx.x > blockIdx.y) return;   // fully-masked causal block

    extern __shared__ __align__(16) char dynRaw[];
    __half* dynh = (__half*)dynRaw;

    const int tid  = threadIdx.x;
    const int wid  = tid >> 5;
    const int lane = tid & 31;
    const int wr   = wid >> 1;     // 4 m-groups of 32
    const int wc   = wid & 1;      // 2 n-groups of 64
    const int m0   = blockIdx.y * 128;
    const int z    = blockIdx.z;
    const int sel  = (MODE == 0) ? (blockIdx.x >> 4) : 0;
    const int n0   = (MODE == 0) ? (blockIdx.x & 15) * 128 : blockIdx.x * 128;

    const __half* A;  int lda;
    const __half* Bm; int ldb;
    int Ktot;
    if (MODE == 0)      { A = g_xh;                      lda = EMB; Bm = g_wh[sel];             ldb = EMB; Ktot = EMB; }
    else if (MODE == 1) { A = g_qh + (size_t)z * SD;     lda = DH;  Bm = g_kh + (size_t)z * SD;  ldb = DH;  Ktot = DH; }
    else if (MODE == 2) { A = g_sh + (size_t)z * SS;     lda = SEQ; Bm = g_vth + (size_t)z * SD; ldb = SEQ; Ktot = m0 + 128; }
    else                { A = g_ctxh;                    lda = EMB; Bm = g_wh[3];               ldb = EMB; Ktot = EMB; }
    const int T = Ktot / BK;

    const uint32_t sbase = smem_u32(dynh);

    // MODE2: per-thread softmax stats for the 4 fragment rows this thread owns
    float mst[4], rlst[4];
    int grow0 = 0;
    if (MODE == 2) {
        grow0 = m0 + wr * 32 + (lane >> 2);     // rows grow0 + {0,8,16,24}
        #pragma unroll
        for (int u = 0; u < 4; u++) {
            int r = grow0 + u * 8;
            mst[u]  = g_m[(size_t)z * SEQ + r];
            rlst[u] = 1.0f / g_l[(size_t)z * SEQ + r];
        }
    }

    auto load_stage = [&](int buf, int t) {
        const int k0 = t * BK;
        const uint32_t sa = sbase + (uint32_t)(buf * STAGE_H) * 2u;
        // A: 128 rows x 32 halves = 512 chunks of 16B, 2/thread
        #pragma unroll
        for (int i = 0; i < 2; i++) {
            int id = tid + i * 256;
            int r = id >> 2, c8 = id & 3;
            cp16(sa + (uint32_t)(r * SA_H + c8 * 8) * 2u,
                 A + (size_t)(m0 + r) * lda + k0 + c8 * 8);
        }
        // B: rows are N-dim, K contiguous
        #pragma unroll
        for (int i = 0; i < 2; i++) {
            int id = tid + i * 256;
            int r = id >> 2, c8 = id & 3;
            cp16(sa + (uint32_t)(B_OFF_H + r * SA_H + c8 * 8) * 2u,
                 Bm + (size_t)(n0 + r) * ldb + k0 + c8 * 8);
        }
        asm volatile("cp.async.commit_group;\n");
    };

    float acc[2][8][4];
    #pragma unroll
    for (int i = 0; i < 2; i++)
        #pragma unroll
        for (int j = 0; j < 8; j++)
            #pragma unroll
            for (int e = 0; e < 4; e++) acc[i][j][e] = 0.0f;

    load_stage(0, 0);
    load_stage(1, 1);

    // ldmatrix addressing (halves)
    const int a_rsel = (lane & 7) + ((lane >> 3) & 1) * 8;
    const int a_ksel = ((lane >> 4) & 1) * 8;
    const int b_nsel = (lane & 7) + ((lane >> 4) & 1) * 8;
    const int b_ksel = ((lane >> 3) & 1) * 8;

    for (int t = 0; t < T; t++) {
        asm volatile("cp.async.wait_group 1;\n" ::: "memory");
        __syncthreads();

        if (t + 2 < T) load_stage((t + 2) % NSTAGE, t + 2);
        else asm volatile("cp.async.commit_group;\n");

        const uint32_t st = sbase + (uint32_t)((t % NSTAGE) * STAGE_H) * 2u;

        #pragma unroll
        for (int ks = 0; ks < 2; ks++) {     // two k16 steps per BK=32
            uint32_t a[2][4], b[8][2];
            #pragma unroll
            for (int i = 0; i < 2; i++)
                ldsm4(a[i], st + (uint32_t)((wr * 32 + i * 16 + a_rsel) * SA_H
                                            + ks * 16 + a_ksel) * 2u);
            #pragma unroll
            for (int u = 0; u < 4; u++) {
                uint32_t r[4];
                ldsm4(r, st + (uint32_t)(B_OFF_H + (wc * 64 + u * 16 + b_nsel) * SA_H
                                         + ks * 16 + b_ksel) * 2u);
                b[2 * u][0] = r[0]; b[2 * u][1] = r[1];
                b[2 * u + 1][0] = r[2]; b[2 * u + 1][1] = r[3];
            }
            if (MODE == 2) {   // fuse softmax exp + causal mask into A fragments
                const int kb = t * 32 + ks * 16 + (lane & 3) * 2;
                #pragma unroll
                for (int i = 0; i < 2; i++)
                    #pragma unroll
                    for (int e = 0; e < 4; e++) {
                        const int u  = i * 2 + (e & 1);          // row slot (+8 per)
                        const int kg = kb + (e >> 1) * 8;        // k of low half
                        const int gr = grow0 + u * 8;            // global row
                        __half2 h2 = *reinterpret_cast<__half2*>(&a[i][e]);
                        float2 f = __half22float2(h2);
                        float p0 = (kg     <= gr) ? __expf((f.x - mst[u]) * INVSQ) * rlst[u] : 0.0f;
                        float p1 = (kg + 1 <= gr) ? __expf((f.y - mst[u]) * INVSQ) * rlst[u] : 0.0f;
                        __half2 r2 = __floats2half2_rn(p0, p1);
                        a[i][e] = *reinterpret_cast<uint32_t*>(&r2);
                    }
            }
            #pragma unroll
            for (int i = 0; i < 2; i++)
                #pragma unroll
                for (int j = 0; j < 8; j++)
                    mma_f16(acc[i][j], a[i], b[j]);
        }
    }

    // ---- epilogue ----
    const int er = lane >> 2;
    const int ec = (lane & 3) * 2;

    if (MODE == 3) {
        float* base = Oext + (size_t)m0 * EMB + n0;
        #pragma unroll
        for (int i = 0; i < 2; i++)
            #pragma unroll
            for (int j = 0; j < 8; j++) {
                int lrow = wr * 32 + i * 16 + er;
                int lcol = wc * 64 + j * 8 + ec;
                float b0 = bias[n0 + lcol], b1 = bias[n0 + lcol + 1];
                *(float2*)(base + (size_t)lrow * EMB + lcol) =
                    make_float2(acc[i][j][0] + b0, acc[i][j][1] + b1);
                *(float2*)(base + (size_t)(lrow + 8) * EMB + lcol) =
                    make_float2(acc[i][j][2] + b0, acc[i][j][3] + b1);
            }
    } else {
        __half* hb; size_t ldo;
        if (MODE == 0) {
            int b = m0 >> 11;
            __half* qkv = (sel == 0 ? g_qh : sel == 1 ? g_kh : g_vh);
            hb = qkv + ((size_t)(b * NH + (blockIdx.x & 15))) * SD + (size_t)(m0 & (SEQ - 1)) * DH;
            ldo = DH;
        } else if (MODE == 1) {
            hb = g_sh + (size_t)z * SS + (size_t)m0 * SEQ + n0;
            ldo = SEQ;
        } else {
            int b = z >> 4, h = z & 15;
            hb = g_ctxh + (size_t)b * SEQ * EMB + (size_t)m0 * EMB + h * DH;
            ldo = EMB;
        }
        #pragma unroll
        for (int i = 0; i < 2; i++)
            #pragma unroll
            for (int j = 0; j < 8; j++) {
                int lrow = wr * 32 + i * 16 + er;
                int lcol = wc * 64 + j * 8 + ec;
                *(__half2*)(hb + (size_t)lrow * ldo + lcol) =
                    __floats2half2_rn(acc[i][j][0], acc[i][j][1]);
                *(__half2*)(hb + (size_t)(lrow + 8) * ldo + lcol) =
                    __floats2half2_rn(acc[i][j][2], acc[i][j][3]);
            }
    }

    // ---- MODE1: per-block softmax partials (pm, pl) from fp32 registers ----
    if (MODE == 1) {
        __syncthreads();                         // pipeline smem dead; reuse
        float* sm_m = (float*)dynRaw;            // [8 warps][32 rows]
        float* sm_l = (float*)dynRaw + 256;

        #pragma unroll
        for (int i = 0; i < 2; i++)
            #pragma unroll
            for (int h = 0; h < 2; h++) {
                const int lrow = wr * 32 + i * 16 + er + h * 8;
                const int grow = m0 + lrow;
                float mx = -1e30f;
                #pragma unroll
                for (int j = 0; j < 8; j++) {
                    int c0 = n0 + wc * 64 + j * 8 + ec;
                    float x0 = (c0     <= grow) ? acc[i][j][h * 2]     : -1e30f;
                    float x1 = (c0 + 1 <= grow) ? acc[i][j][h * 2 + 1] : -1e30f;
                    mx = fmaxf(mx, fmaxf(x0, x1));
                }
                mx = fmaxf(mx, __shfl_xor_sync(0xFFFFFFFFu, mx, 1));
                mx = fmaxf(mx, __shfl_xor_sync(0xFFFFFFFFu, mx, 2));
                float sum = 0.0f;
                #pragma unroll
                for (int j = 0; j < 8; j++) {
                    int c0 = n0 + wc * 64 + j * 8 + ec;
                    if (c0     <= grow) sum += __expf((acc[i][j][h * 2]     - mx) * INVSQ);
                    if (c0 + 1 <= grow) sum += __expf((acc[i][j][h * 2 + 1] - mx) * INVSQ);
                }
                sum += __shfl_xor_sync(0xFFFFFFFFu, sum, 1);
                sum += __shfl_xor_sync(0xFFFFFFFFu, sum, 2);
                if ((lane & 3) == 0) {
                    int rl32 = i * 16 + er + h * 8;
                    sm_m[wid * 32 + rl32] = mx;
                    sm_l[wid * 32 + rl32] = sum;
                }
            }
        __syncthreads();
        if (tid < 128) {
            int r = tid, wrg = r >> 5, rl32 = r & 31;
            float ma = sm_m[(wrg * 2) * 32 + rl32];
            float mb = sm_m[(wrg * 2 + 1) * 32 + rl32];
            float mm = fmaxf(ma, mb);
            float ll = __expf((ma - mm) * INVSQ) * sm_l[(wrg * 2) * 32 + rl32]
                     + __expf((mb - mm) * INVSQ) * sm_l[(wrg * 2 + 1) * 32 + rl32];
            size_t off = ((size_t)z * 16 + blockIdx.x) * SEQ + m0 + r;
            g_pm[off] = mm;
            g_pl[off] = ll;
        }
    }
}

// ---------------------------------------------------------------------------
// combine per-block partials into per-row softmax stats (m, l)
// ---------------------------------------------------------------------------
__global__ __launch_bounds__(256)
void combine_stats()
{
    int idx = blockIdx.x * 256 + threadIdx.x;   // 0 .. BH*SEQ-1
    int z = idx >> 11;
    int q = idx & (SEQ - 1);
    int nb = (q >> 7) + 1;

    float m = -1e30f;
    for (int b = 0; b < nb; b++)
        m = fmaxf(m, g_pm[((size_t)z * 16 + b) * SEQ + q]);
    float l = 0.0f;
    for (int b = 0; b < nb; b++) {
        size_t off = ((size_t)z * 16 + b) * SEQ + q;
        l += __expf((g_pm[off] - m) * INVSQ) * g_pl[off];
    }
    g_m[(size_t)z * SEQ + q] = m;
    g_l[(size_t)z * SEQ + q] = l;
}

// ---------------------------------------------------------------------------
// convert inputs to fp16: x -> g_xh, Wq/Wk/Wv/Wo -> g_wh[0..3]
// ---------------------------------------------------------------------------
__global__ __launch_bounds__(256)
void cvt_inputs(const float4* __restrict__ x,  const float4* __restrict__ wq,
                const float4* __restrict__ wk, const float4* __restrict__ wv,
                const float4* __restrict__ wo)
{
    const int XC = BATCH * SEQ * EMB / 4;   // 4194304
    const int WC = EMB * EMB / 4;           // 1048576
    int i = blockIdx.x * 256 + threadIdx.x;
    float4 v; __half* dst;
    if (i < XC) { v = x[i]; dst = g_xh + (size_t)i * 4; }
    else {
        int r = i - XC;
        int s = r / WC, o = r - s * WC;
        const float4* w = (s == 0 ? wq : s == 1 ? wk : s == 2 ? wv : wo);
        v = w[o]; dst = g_wh[s] + (size_t)o * 4;
    }
    *(__half2*)dst       = __floats2half2_rn(v.x, v.y);
    *(__half2*)(dst + 2) = __floats2half2_rn(v.z, v.w);
}

// ---------------------------------------------------------------------------
// V transpose: g_vh [bh][k][dh] -> g_vth [bh][dh][k], fp16 32x32 tiles
// ---------------------------------------------------------------------------
__global__ __launch_bounds__(256)
void transpose_v()
{
    __shared__ __half tile[32][33];
    const int z  = blockIdx.z;
    const int k0 = blockIdx.x * 32;
    const int n0 = blockIdx.y * 32;
    const int tx = threadIdx.x & 31;
    const int ty = threadIdx.x >> 5;      // 8 rows per pass

    const __half* src = g_vh + (size_t)z * SD;
    #pragma unroll
    for (int j = 0; j < 4; j++)
        tile[ty + j * 8][tx] = src[(size_t)(k0 + ty + j * 8) * DH + n0 + tx];
    __syncthreads();
    __half* dst = g_vth + (size_t)z * SD;
    #pragma unroll
    for (int j = 0; j < 4; j++)
        dst[(size_t)(n0 + ty + j * 8) * SEQ + k0 + tx] = tile[tx][ty + j * 8];
}

extern "C" void kernel_launch(void* const* d_in, const int* in_sizes, int n_in,
                              void* d_out, int out_size)
{
    const float* x  = (const float*)d_in[0];
    const float* Wq = (const float*)d_in[1];
    const float* Wk = (const float*)d_in[2];
    const float* Wv = (const float*)d_in[3];
    const float* Wo = (const float*)d_in[4];
    const float* bo = (const float*)d_in[5];
    float* out = (float*)d_out;

    cudaFuncSetAttribute(gemm_tc<0>, cudaFuncAttributeMaxDynamicSharedMemorySize, SMEM_BYTES);
    cudaFuncSetAttribute(gemm_tc<1>, cudaFuncAttributeMaxDynamicSharedMemorySize, SMEM_BYTES);
    cudaFuncSetAttribute(gemm_tc<2>, cudaFuncAttributeMaxDynamicSharedMemorySize, SMEM_BYTES);
    cudaFuncSetAttribute(gemm_tc<3>, cudaFuncAttributeMaxDynamicSharedMemorySize, SMEM_BYTES);

    dim3 blk(256);
    const int XC = BATCH * SEQ * EMB / 4;
    const int WC = EMB * EMB / 4;

    // fp32 -> fp16 inputs
    cvt_inputs<<<(XC + 4 * WC) / 256, blk>>>((const float4*)x, (const float4*)Wq,
                                             (const float4*)Wk, (const float4*)Wv,
                                             (const float4*)Wo);

    // fused QKV: grid.x = 48 (3 weights x 16 head tiles)
    gemm_tc<0><<<dim3(48, 64, 1), blk, SMEM_BYTES>>>(nullptr, nullptr);

    // V transpose for MODE2's B operand
    transpose_v<<<dim3(SEQ / 32, DH / 32, BH), blk>>>();

    // scores = Q K^T per (b,h) + in-epilogue softmax partials
    gemm_tc<1><<<dim3(16, 16, BH), blk, SMEM_BYTES>>>(nullptr, nullptr);

    // combine partials -> per-row (m, l)
    combine_stats<<<BH * SEQ / 256, 256>>>();

    // ctx = softmax(S) V per (b,h); exp fused into A fragments
    gemm_tc<2><<<dim3(1, 16, BH), blk, SMEM_BYTES>>>(nullptr, nullptr);

    // out = ctx Wo^T + bias (fp32 out)
    gemm_tc<3><<<dim3(16, 64, 1), blk, SMEM_BYTES>>>(out, bo);
}